// round 1
// baseline (speedup 1.0000x reference)
#include <cuda_runtime.h>
#include <cuda_bf16.h>
#include <math.h>

#define DV 33
#define D2 (DV*DV)        // 1089
#define D3 (DV*DV*DV)     // 35937
#define NLUT (3*D3)       // 107811
#define B 4
#define NPIX (1024*1024)

// ---------------- scratch (static device allocations are allowed) -------------
__device__ float g_resized[B*3*256*256];
__device__ float g_x1[B*16*128*128];
__device__ float g_x2[B*32*64*64];
__device__ float g_x3[B*64*32*32];
__device__ float g_x4[B*128*16*16];
__device__ float g_codes[B*512];
__device__ float g_ss1[B*16*2];
__device__ float g_ss2[B*32*2];
__device__ float g_ss3[B*64*2];
__device__ float g_ss4[B*128*2];
__device__ float g_wts[B*3];
__device__ float g_verts[B*3*DV];
__device__ float g_luts[B*NLUT];

// ---------------- resize: 1024 -> 256, scale 4, half-pixel => avg of 2x2 @(+1,+1)
__global__ void resize_k(const float* __restrict__ lq, float* __restrict__ out)
{
    int idx = blockIdx.x * blockDim.x + threadIdx.x;
    if (idx >= B*3*256*256) return;
    int ox = idx & 255;
    int oy = (idx >> 8) & 255;
    int bc = idx >> 16;
    const float* ip = lq + (size_t)bc * 1024 * 1024 + (size_t)(4*oy+1)*1024 + (4*ox+1);
    out[idx] = 0.25f * (ip[0] + ip[1] + ip[1024] + ip[1025]);
}

// ---------------- conv: k3 s2 p1 + LeakyReLU, with affine-on-load (prev IN folded)
template<int IC, int OC, int OCB, int INHW, int OUTHW>
__global__ void conv_k(const float* __restrict__ in, const float* __restrict__ w,
                       const float* __restrict__ bias, const float* __restrict__ ss,
                       float* __restrict__ out)
{
    const int b = blockIdx.z;
    const int ocg = blockIdx.y;
    __shared__ float sw[OCB*IC*9];
    __shared__ float ssc[IC];
    __shared__ float ssh[IC];
    for (int i = threadIdx.x; i < OCB*IC*9; i += blockDim.x) {
        int o = i / (IC*9);
        sw[i] = w[(ocg*OCB + o)*IC*9 + (i % (IC*9))];
    }
    for (int i = threadIdx.x; i < IC; i += blockDim.x) {
        if (ss) { ssc[i] = ss[(b*IC+i)*2]; ssh[i] = ss[(b*IC+i)*2+1]; }
        else    { ssc[i] = 1.f;            ssh[i] = 0.f; }
    }
    __syncthreads();
    const int spatial = OUTHW*OUTHW;
    const float* inb = in + (size_t)b*IC*INHW*INHW;
    for (int p = blockIdx.x*blockDim.x + threadIdx.x; p < spatial; p += gridDim.x*blockDim.x) {
        int oy = p / OUTHW, ox = p % OUTHW;
        float acc[OCB];
        #pragma unroll
        for (int o = 0; o < OCB; o++) acc[o] = bias[ocg*OCB+o];
        for (int ic = 0; ic < IC; ic++) {
            const float* ip = inb + (size_t)ic*INHW*INHW;
            float s = ssc[ic], sh = ssh[ic];
            #pragma unroll
            for (int ky = 0; ky < 3; ky++) {
                int iy = 2*oy - 1 + ky;
                if (iy < 0 || iy >= INHW) continue;
                #pragma unroll
                for (int kx = 0; kx < 3; kx++) {
                    int ix = 2*ox - 1 + kx;
                    if (ix < 0 || ix >= INHW) continue;
                    float v = fmaf(ip[iy*INHW+ix], s, sh);
                    #pragma unroll
                    for (int o = 0; o < OCB; o++)
                        acc[o] = fmaf(v, sw[(o*IC+ic)*9 + ky*3+kx], acc[o]);
                }
            }
        }
        #pragma unroll
        for (int o = 0; o < OCB; o++) {
            float y = acc[o];
            y = y >= 0.f ? y : 0.2f*y;
            out[(((size_t)b*OC + ocg*OCB + o)*OUTHW + oy)*OUTHW + ox] = y;
        }
    }
}

// ---------------- instance-norm stats -> per-(b,c) scale/shift ----------------
__global__ void stats_k(const float* __restrict__ x, int spatial, int C,
                        const float* __restrict__ gamma, const float* __restrict__ beta,
                        float* __restrict__ ss)
{
    int bc = blockIdx.x;           // b*C + c
    int c = bc % C;
    const float* xp = x + (size_t)bc * spatial;
    double s = 0.0, s2 = 0.0;
    for (int i = threadIdx.x; i < spatial; i += blockDim.x) {
        float v = xp[i];
        s += (double)v;
        s2 += (double)v * (double)v;
    }
    __shared__ double rs[256], rs2[256];
    rs[threadIdx.x] = s; rs2[threadIdx.x] = s2;
    __syncthreads();
    for (int st = 128; st > 0; st >>= 1) {
        if (threadIdx.x < st) { rs[threadIdx.x] += rs[threadIdx.x+st]; rs2[threadIdx.x] += rs2[threadIdx.x+st]; }
        __syncthreads();
    }
    if (threadIdx.x == 0) {
        double mean = rs[0] / spatial;
        double var  = rs2[0] / spatial - mean*mean;
        float scale = gamma[c] * rsqrtf((float)var + 1e-5f);
        float shift = beta[c] - (float)mean * scale;
        ss[bc*2]   = scale;
        ss[bc*2+1] = shift;
    }
}

// ---------------- conv5 (no IN after) + LeakyReLU + adaptive-avgpool(2) -> codes
__global__ void conv5_pool_k(const float* __restrict__ in, const float* __restrict__ w,
                             const float* __restrict__ bias, const float* __restrict__ ss,
                             float* __restrict__ codes)
{
    const int IC = 128, OCB = 4;
    int b = blockIdx.y, ocg = blockIdx.x;   // 32 groups of 4 oc
    __shared__ float sw[OCB*IC*9];
    __shared__ float ssc[IC], ssh[IC];
    __shared__ float sred[OCB][64];
    for (int i = threadIdx.x; i < OCB*IC*9; i += blockDim.x) {
        int o = i / (IC*9);
        sw[i] = w[(ocg*OCB + o)*IC*9 + (i % (IC*9))];
    }
    for (int i = threadIdx.x; i < IC; i += blockDim.x) {
        ssc[i] = ss[(b*IC+i)*2]; ssh[i] = ss[(b*IC+i)*2+1];
    }
    __syncthreads();
    int t = threadIdx.x;          // 64 threads, one output pixel each (8x8)
    int oy = t >> 3, ox = t & 7;
    float acc[OCB];
    #pragma unroll
    for (int o = 0; o < OCB; o++) acc[o] = bias[ocg*OCB+o];
    const float* inb = in + (size_t)b*IC*16*16;
    for (int ic = 0; ic < IC; ic++) {
        const float* ip = inb + ic*16*16;
        float s = ssc[ic], sh = ssh[ic];
        #pragma unroll
        for (int ky = 0; ky < 3; ky++) {
            int iy = 2*oy - 1 + ky;
            if (iy < 0 || iy >= 16) continue;
            #pragma unroll
            for (int kx = 0; kx < 3; kx++) {
                int ix = 2*ox - 1 + kx;
                if (ix < 0 || ix >= 16) continue;
                float v = fmaf(ip[iy*16+ix], s, sh);
                #pragma unroll
                for (int o = 0; o < OCB; o++)
                    acc[o] = fmaf(v, sw[(o*IC+ic)*9 + ky*3+kx], acc[o]);
            }
        }
    }
    #pragma unroll
    for (int o = 0; o < OCB; o++) {
        float y = acc[o];
        sred[o][t] = (y >= 0.f ? y : 0.2f*y);
    }
    __syncthreads();
    if (t < OCB*4) {
        int o = t >> 2, q = t & 3, py = q >> 1, px = q & 1;
        float s = 0.f;
        #pragma unroll
        for (int yy = 0; yy < 4; yy++)
            #pragma unroll
            for (int xx = 0; xx < 4; xx++)
                s += sred[o][(py*4+yy)*8 + (px*4+xx)];
        codes[b*512 + (ocg*OCB + o)*4 + q] = s * (1.f/16.f);
    }
}

// ---------------- LUT weights + AdaInt vertices ------------------------------
__global__ void mlp_k(const float* __restrict__ codes,
                      const float* __restrict__ lw, const float* __restrict__ lb,
                      const float* __restrict__ aw, const float* __restrict__ ab,
                      float* __restrict__ wts, float* __restrict__ verts,
                      float* __restrict__ out_w, float* __restrict__ out_v)
{
    int b = blockIdx.x;
    __shared__ float sc[512];
    __shared__ float pre[96];
    for (int i = threadIdx.x; i < 512; i += blockDim.x) sc[i] = codes[b*512 + i];
    __syncthreads();
    int t = threadIdx.x;
    if (t < 96) {
        float acc = ab[t];
        const float* ar = aw + t*512;
        for (int k = 0; k < 512; k++) acc = fmaf(sc[k], ar[k], acc);
        pre[t] = acc;
    } else if (t < 99) {
        int r = t - 96;
        float acc = lb[r];
        const float* lr = lw + r*512;
        for (int k = 0; k < 512; k++) acc = fmaf(sc[k], lr[k], acc);
        wts[b*3 + r] = acc;
        out_w[b*3 + r] = acc;
    }
    __syncthreads();
    int warp = t >> 5, lane = t & 31;
    if (warp < 3) {
        float x = pre[warp*32 + lane];
        float m = x;
        #pragma unroll
        for (int off = 16; off; off >>= 1) m = fmaxf(m, __shfl_xor_sync(0xffffffffu, m, off));
        float e = expf(x - m);
        float ssum = e;
        #pragma unroll
        for (int off = 16; off; off >>= 1) ssum += __shfl_xor_sync(0xffffffffu, ssum, off);
        float p = e / ssum;
        float cs = p;
        #pragma unroll
        for (int off = 1; off < 32; off <<= 1) {
            float v = __shfl_up_sync(0xffffffffu, cs, off);
            if (lane >= off) cs += v;
        }
        float* vp = verts + (b*3 + warp)*DV;
        float* vo = out_v + (b*3 + warp)*DV;
        if (lane == 0) { vp[0] = 0.f; vo[0] = 0.f; }
        vp[lane+1] = cs;
        vo[lane+1] = cs;
    }
}

// ---------------- lut synthesis: luts[b,i] = sum_r wts[b,r] * bw[i,r] ----------
__global__ void luts_k(const float* __restrict__ bw, const float* __restrict__ wts,
                       float* __restrict__ luts)
{
    int i = blockIdx.x*blockDim.x + threadIdx.x;
    if (i >= B*NLUT) return;
    int b = i / NLUT, j = i - b*NLUT;
    float w0 = wts[b*3], w1 = wts[b*3+1], w2 = wts[b*3+2];
    const float* br = bw + (size_t)j*3;
    luts[i] = fmaf(w0, br[0], fmaf(w1, br[1], w2*br[2]));
}

// ---------------- AiLUT transform: searchsorted + trilerp + clip --------------
__global__ void transform_k(const float* __restrict__ lq, const float* __restrict__ luts,
                            const float* __restrict__ verts, float* __restrict__ out)
{
    const int BLOCKS_PER_B = NPIX / 256;         // 4096
    int b = blockIdx.x / BLOCKS_PER_B;
    int n = (blockIdx.x - b*BLOCKS_PER_B)*256 + threadIdx.x;
    __shared__ float sv[3*DV];
    if (threadIdx.x < 3*DV) sv[threadIdx.x] = verts[b*3*DV + threadIdx.x];
    __syncthreads();

    const float* lqb = lq + (size_t)b*3*NPIX;
    float pix0 = lqb[n];
    float pix1 = lqb[NPIX + n];
    float pix2 = lqb[2*NPIX + n];

    float coord[3];
    float px[3] = {pix0, pix1, pix2};
    #pragma unroll
    for (int ch = 0; ch < 3; ch++) {
        const float* v = sv + ch*DV;
        float x = px[ch];
        int lo = 0, hi = DV;
        while (lo < hi) {
            int m = (lo + hi) >> 1;
            if (v[m] <= x) lo = m + 1; else hi = m;
        }
        int idx = min(max(lo, 1), DV-1);
        float vl = v[idx-1], vh = v[idx];
        float fr = (x - vl) / (vh - vl + 1e-8f);
        float cd = (float)(idx - 1) + fr;
        coord[ch] = fminf(fmaxf(cd, 0.f), (float)(DV-1));
    }
    int i0 = min((int)coord[0], DV-2);
    int j0 = min((int)coord[1], DV-2);
    int k0 = min((int)coord[2], DV-2);
    float fr = coord[0] - (float)i0;
    float fg = coord[1] - (float)j0;
    float fb = coord[2] - (float)k0;
    float gr = 1.f - fr, gg = 1.f - fg, gb = 1.f - fb;
    float w000 = gr*gg*gb, w001 = gr*gg*fb, w010 = gr*fg*gb, w011 = gr*fg*fb;
    float w100 = fr*gg*gb, w101 = fr*gg*fb, w110 = fr*fg*gb, w111 = fr*fg*fb;

    const float* L = luts + (size_t)b*NLUT + i0*D2 + j0*DV + k0;
    float* ob = out + (size_t)b*3*NPIX + n;
    #pragma unroll
    for (int c = 0; c < 3; c++) {
        const float* Lc = L + c*D3;
        float r = Lc[0]    * w000 + Lc[1]    * w001
                + Lc[DV]   * w010 + Lc[DV+1] * w011
                + Lc[D2]   * w100 + Lc[D2+1] * w101
                + Lc[D2+DV]* w110 + Lc[D2+DV+1]*w111;
        ob[(size_t)c*NPIX] = fminf(fmaxf(r, 0.f), 1.f);
    }
}

// ---------------- host launcher ----------------------------------------------
extern "C" void kernel_launch(void* const* d_in, const int* in_sizes, int n_in,
                              void* d_out, int out_size)
{
    const float* lq  = (const float*)d_in[0];
    const float* w1  = (const float*)d_in[1];
    const float* b1  = (const float*)d_in[2];
    const float* g1  = (const float*)d_in[3];
    const float* be1 = (const float*)d_in[4];
    const float* w2  = (const float*)d_in[5];
    const float* b2  = (const float*)d_in[6];
    const float* g2  = (const float*)d_in[7];
    const float* be2 = (const float*)d_in[8];
    const float* w3  = (const float*)d_in[9];
    const float* b3  = (const float*)d_in[10];
    const float* g3  = (const float*)d_in[11];
    const float* be3 = (const float*)d_in[12];
    const float* w4  = (const float*)d_in[13];
    const float* b4  = (const float*)d_in[14];
    const float* g4  = (const float*)d_in[15];
    const float* be4 = (const float*)d_in[16];
    const float* w5  = (const float*)d_in[17];
    const float* b5  = (const float*)d_in[18];
    const float* lw  = (const float*)d_in[19];
    const float* lb  = (const float*)d_in[20];
    const float* bw  = (const float*)d_in[21];
    const float* aw  = (const float*)d_in[22];
    const float* ab  = (const float*)d_in[23];

    float *res, *x1, *x2, *x3, *x4, *codes, *ss1, *ss2, *ss3, *ss4, *wts, *verts, *luts;
    cudaGetSymbolAddress((void**)&res,   g_resized);
    cudaGetSymbolAddress((void**)&x1,    g_x1);
    cudaGetSymbolAddress((void**)&x2,    g_x2);
    cudaGetSymbolAddress((void**)&x3,    g_x3);
    cudaGetSymbolAddress((void**)&x4,    g_x4);
    cudaGetSymbolAddress((void**)&codes, g_codes);
    cudaGetSymbolAddress((void**)&ss1,   g_ss1);
    cudaGetSymbolAddress((void**)&ss2,   g_ss2);
    cudaGetSymbolAddress((void**)&ss3,   g_ss3);
    cudaGetSymbolAddress((void**)&ss4,   g_ss4);
    cudaGetSymbolAddress((void**)&wts,   g_wts);
    cudaGetSymbolAddress((void**)&verts, g_verts);
    cudaGetSymbolAddress((void**)&luts,  g_luts);

    float* out = (float*)d_out;
    const int OFF_W = B*3*NPIX;          // 12582912
    const int OFF_V = OFF_W + B*3;       // +12

    resize_k<<<(B*3*256*256 + 255)/256, 256>>>(lq, res);

    conv_k<3, 16, 16, 256, 128><<<dim3(64, 1, B), 256>>>(res, w1, b1, nullptr, x1);
    stats_k<<<B*16, 256>>>(x1, 128*128, 16, g1, be1, ss1);

    conv_k<16, 32, 8, 128, 64><<<dim3(16, 4, B), 256>>>(x1, w2, b2, ss1, x2);
    stats_k<<<B*32, 256>>>(x2, 64*64, 32, g2, be2, ss2);

    conv_k<32, 64, 8, 64, 32><<<dim3(4, 8, B), 256>>>(x2, w3, b3, ss2, x3);
    stats_k<<<B*64, 256>>>(x3, 32*32, 64, g3, be3, ss3);

    conv_k<64, 128, 8, 32, 16><<<dim3(1, 16, B), 256>>>(x3, w4, b4, ss3, x4);
    stats_k<<<B*128, 256>>>(x4, 16*16, 128, g4, be4, ss4);

    conv5_pool_k<<<dim3(32, B), 64>>>(x4, w5, b5, ss4, codes);

    mlp_k<<<B, 128>>>(codes, lw, lb, aw, ab, wts, verts, out + OFF_W, out + OFF_V);

    luts_k<<<(B*NLUT + 255)/256, 256>>>(bw, wts, luts);

    transform_k<<<B*(NPIX/256), 256>>>(lq, luts, verts, out);
}

// round 2
// speedup vs baseline: 1.5617x; 1.5617x over previous
#include <cuda_runtime.h>
#include <cuda_bf16.h>
#include <math.h>

#define DV 33
#define D2 (DV*DV)        // 1089
#define D3 (DV*DV*DV)     // 35937
#define NLUT (3*D3)       // 107811
#define B 4
#define NPIX (1024*1024)

// ---------------- scratch ----------------------------------------------------
__device__ float g_resized[B*3*256*256];
__device__ float g_x1[B*16*128*128];
__device__ float g_x2[B*32*64*64];
__device__ float g_x3[B*64*32*32];
__device__ float g_x4[B*128*16*16];
__device__ float g_codes[B*512];
// raw stats: per (b,c): [sum, sumsq]; combined buffer
// ss1 @0 (4*16*2=128), ss2 @128 (256), ss3 @384 (512), ss4 @896 (1024)
__device__ float g_stats[1920];
__device__ float g_wts[B*3];
__device__ float g_verts[B*3*DV];
__device__ float2 g_luts2[B*NLUT];

__global__ void zero_k(float* p, int n)
{
    int i = blockIdx.x*blockDim.x + threadIdx.x;
    if (i < n) p[i] = 0.f;
}

// ---------------- resize: 1024 -> 256, scale 4, half-pixel => avg of 2x2 @(+1,+1)
__global__ void resize_k(const float* __restrict__ lq, float* __restrict__ out)
{
    int idx = blockIdx.x * blockDim.x + threadIdx.x;
    if (idx >= B*3*256*256) return;
    int ox = idx & 255;
    int oy = (idx >> 8) & 255;
    int bc = idx >> 16;
    const float* ip = lq + (size_t)bc * 1024 * 1024 + (size_t)(4*oy+1)*1024 + (4*ox+1);
    out[idx] = 0.25f * (ip[0] + ip[1] + ip[1024] + ip[1025]);
}

// ---------------- conv: k3 s2 p1 + LeakyReLU; IN folded on load; raw stats out
// For k3/s2/p1 with INHW=2*OUTHW the only invalid taps are iy==-1 (oy==0,ky==0)
// and ix==-1 (ox==0,kx==0). Branch-free predicated loads.
template<int IC, int OC, int OCB, int INHW, int OUTHW, bool HAS_IN>
__global__ void conv_k(const float* __restrict__ in, const float* __restrict__ w,
                       const float* __restrict__ bias,
                       const float* __restrict__ stat_in,
                       const float* __restrict__ gamma, const float* __restrict__ beta,
                       float* __restrict__ stat_out,
                       float* __restrict__ out)
{
    const int b = blockIdx.z;
    const int ocg = blockIdx.y;
    const int tid = threadIdx.x;
    __shared__ float sw[IC*9*OCB];
    __shared__ float ssc[IC];
    __shared__ float ssh[IC];
    for (int i = tid; i < IC*9*OCB; i += 256) {
        int o = i % OCB, t = i / OCB;
        int k = t % 9, ic = t / 9;
        sw[i] = w[((ocg*OCB + o)*IC + ic)*9 + k];
    }
    if (HAS_IN) {
        for (int i = tid; i < IC; i += 256) {
            const float invn = 1.f / (float)(INHW*INHW);
            float s1 = stat_in[(b*IC+i)*2], s2 = stat_in[(b*IC+i)*2+1];
            float mean = s1 * invn;
            float var  = s2 * invn - mean*mean;
            float sc = gamma[i] * rsqrtf(var + 1e-5f);
            ssc[i] = sc;
            ssh[i] = beta[i] - mean * sc;
        }
    }
    __syncthreads();

    int p = blockIdx.x*256 + tid;         // exact: OUTHW*OUTHW multiple of 256
    int oy = p / OUTHW, ox = p % OUTHW;
    float acc[OCB];
    #pragma unroll
    for (int o = 0; o < OCB; o++) acc[o] = bias[ocg*OCB+o];

    const float* inb = in + (size_t)b*IC*INHW*INHW + (2*oy-1)*INHW + (2*ox-1);
    const bool okT = (oy > 0);
    const bool okL = (ox > 0);

    for (int ic = 0; ic < IC; ic++) {
        const float* ip = inb + (size_t)ic*INHW*INHW;
        float v[9];
        #pragma unroll
        for (int ky = 0; ky < 3; ky++) {
            #pragma unroll
            for (int kx = 0; kx < 3; kx++) {
                bool ok = (okT || ky > 0) && (okL || kx > 0);
                float t = ok ? ip[ky*INHW+kx] : 0.f;
                v[ky*3+kx] = t;
            }
        }
        if (HAS_IN) {
            float s = ssc[ic], sh = ssh[ic];
            #pragma unroll
            for (int ky = 0; ky < 3; ky++)
                #pragma unroll
                for (int kx = 0; kx < 3; kx++) {
                    bool ok = (okT || ky > 0) && (okL || kx > 0);
                    v[ky*3+kx] = ok ? fmaf(v[ky*3+kx], s, sh) : 0.f;
                }
        }
        #pragma unroll
        for (int k = 0; k < 9; k++) {
            float t = v[k];
            #pragma unroll
            for (int o = 0; o < OCB; o++)
                acc[o] = fmaf(t, sw[(ic*9+k)*OCB+o], acc[o]);
        }
    }

    float ys[OCB];
    #pragma unroll
    for (int o = 0; o < OCB; o++) {
        float y = acc[o];
        y = y >= 0.f ? y : 0.2f*y;
        ys[o] = y;
        out[(((size_t)b*OC + ocg*OCB + o)*OUTHW)*OUTHW + p] = y;
    }

    // ------ fused stats: block-reduce sum/sumsq per oc, one atomic pair/block
    float s1[OCB], s2[OCB];
    #pragma unroll
    for (int o = 0; o < OCB; o++) { s1[o] = ys[o]; s2[o] = ys[o]*ys[o]; }
    #pragma unroll
    for (int o = 0; o < OCB; o++) {
        #pragma unroll
        for (int off = 16; off; off >>= 1) {
            s1[o] += __shfl_xor_sync(0xffffffffu, s1[o], off);
            s2[o] += __shfl_xor_sync(0xffffffffu, s2[o], off);
        }
    }
    __shared__ float2 red[OCB][8];
    int warp = tid >> 5, lane = tid & 31;
    if (lane == 0) {
        #pragma unroll
        for (int o = 0; o < OCB; o++) red[o][warp] = make_float2(s1[o], s2[o]);
    }
    __syncthreads();
    if (tid < OCB) {
        float a = 0.f, c = 0.f;
        #pragma unroll
        for (int wdx = 0; wdx < 8; wdx++) { a += red[tid][wdx].x; c += red[tid][wdx].y; }
        int bc = b*OC + ocg*OCB + tid;
        atomicAdd(stat_out + bc*2, a);
        atomicAdd(stat_out + bc*2+1, c);
    }
}

// ---------------- conv5 (no IN after) + LeakyReLU + adaptive-avgpool(2) -> codes
__global__ void conv5_pool_k(const float* __restrict__ in, const float* __restrict__ w,
                             const float* __restrict__ bias,
                             const float* __restrict__ stat_in,
                             const float* __restrict__ gamma, const float* __restrict__ beta,
                             float* __restrict__ codes)
{
    const int IC = 128, OCB = 4;
    int b = blockIdx.y, ocg = blockIdx.x;   // 32 groups of 4 oc
    __shared__ float sw[OCB*IC*9];
    __shared__ float ssc[IC], ssh[IC];
    __shared__ float sred[OCB][64];
    for (int i = threadIdx.x; i < OCB*IC*9; i += blockDim.x) {
        int o = i / (IC*9);
        sw[i] = w[(ocg*OCB + o)*IC*9 + (i % (IC*9))];
    }
    for (int i = threadIdx.x; i < IC; i += blockDim.x) {
        const float invn = 1.f / 256.f;
        float s1 = stat_in[(b*IC+i)*2], s2 = stat_in[(b*IC+i)*2+1];
        float mean = s1 * invn;
        float var  = s2 * invn - mean*mean;
        float sc = gamma[i] * rsqrtf(var + 1e-5f);
        ssc[i] = sc;
        ssh[i] = beta[i] - mean * sc;
    }
    __syncthreads();
    int t = threadIdx.x;          // 64 threads, one output pixel each (8x8)
    int oy = t >> 3, ox = t & 7;
    float acc[OCB];
    #pragma unroll
    for (int o = 0; o < OCB; o++) acc[o] = bias[ocg*OCB+o];
    const float* inb = in + (size_t)b*IC*16*16 + (2*oy-1)*16 + (2*ox-1);
    const bool okT = (oy > 0), okL = (ox > 0);
    for (int ic = 0; ic < IC; ic++) {
        const float* ip = inb + ic*256;
        float s = ssc[ic], sh = ssh[ic];
        float v[9];
        #pragma unroll
        for (int ky = 0; ky < 3; ky++)
            #pragma unroll
            for (int kx = 0; kx < 3; kx++) {
                bool ok = (okT || ky > 0) && (okL || kx > 0);
                float u = ok ? ip[ky*16+kx] : 0.f;
                v[ky*3+kx] = ok ? fmaf(u, s, sh) : 0.f;
            }
        #pragma unroll
        for (int k = 0; k < 9; k++) {
            float u = v[k];
            #pragma unroll
            for (int o = 0; o < OCB; o++)
                acc[o] = fmaf(u, sw[(o*IC+ic)*9 + k], acc[o]);
        }
    }
    #pragma unroll
    for (int o = 0; o < OCB; o++) {
        float y = acc[o];
        sred[o][t] = (y >= 0.f ? y : 0.2f*y);
    }
    __syncthreads();
    if (t < OCB*4) {
        int o = t >> 2, q = t & 3, py = q >> 1, px = q & 1;
        float s = 0.f;
        #pragma unroll
        for (int yy = 0; yy < 4; yy++)
            #pragma unroll
            for (int xx = 0; xx < 4; xx++)
                s += sred[o][(py*4+yy)*8 + (px*4+xx)];
        codes[b*512 + (ocg*OCB + o)*4 + q] = s * (1.f/16.f);
    }
}

// ---------------- LUT weights + AdaInt vertices ------------------------------
__global__ void mlp_k(const float* __restrict__ codes,
                      const float* __restrict__ lw, const float* __restrict__ lb,
                      const float* __restrict__ aw, const float* __restrict__ ab,
                      float* __restrict__ wts, float* __restrict__ verts,
                      float* __restrict__ out_w, float* __restrict__ out_v)
{
    int b = blockIdx.x;
    __shared__ float sc[512];
    __shared__ float pre[96];
    for (int i = threadIdx.x; i < 512; i += blockDim.x) sc[i] = codes[b*512 + i];
    __syncthreads();
    int t = threadIdx.x;
    if (t < 96) {
        float acc = ab[t];
        const float* ar = aw + t*512;
        for (int k = 0; k < 512; k++) acc = fmaf(sc[k], ar[k], acc);
        pre[t] = acc;
    } else if (t < 99) {
        int r = t - 96;
        float acc = lb[r];
        const float* lr = lw + r*512;
        for (int k = 0; k < 512; k++) acc = fmaf(sc[k], lr[k], acc);
        wts[b*3 + r] = acc;
        out_w[b*3 + r] = acc;
    }
    __syncthreads();
    int warp = t >> 5, lane = t & 31;
    if (warp < 3) {
        float x = pre[warp*32 + lane];
        float m = x;
        #pragma unroll
        for (int off = 16; off; off >>= 1) m = fmaxf(m, __shfl_xor_sync(0xffffffffu, m, off));
        float e = expf(x - m);
        float ssum = e;
        #pragma unroll
        for (int off = 16; off; off >>= 1) ssum += __shfl_xor_sync(0xffffffffu, ssum, off);
        float p = e / ssum;
        float cs = p;
        #pragma unroll
        for (int off = 1; off < 32; off <<= 1) {
            float v = __shfl_up_sync(0xffffffffu, cs, off);
            if (lane >= off) cs += v;
        }
        float* vp = verts + (b*3 + warp)*DV;
        float* vo = out_v + (b*3 + warp)*DV;
        if (lane == 0) { vp[0] = 0.f; vo[0] = 0.f; }
        vp[lane+1] = cs;
        vo[lane+1] = cs;
    }
}

// ---------------- lut synthesis into paired-float2 layout --------------------
// pair i (flat index over [b][c][i][j][k]) holds (L[k], L[k+1])
__global__ void luts2_k(const float* __restrict__ bw, const float* __restrict__ wts,
                        float2* __restrict__ lut2)
{
    int i = blockIdx.x*blockDim.x + threadIdx.x;
    if (i >= B*NLUT) return;
    int b = i / NLUT, j = i - b*NLUT;
    float w0 = wts[b*3], w1 = wts[b*3+1], w2 = wts[b*3+2];
    const float* br = bw + (size_t)j*3;
    float v = fmaf(w0, br[0], fmaf(w1, br[1], w2*br[2]));
    int k = j % DV;
    lut2[i].x = v;
    if (k > 0) lut2[i-1].y = v;
}

// ---------------- AiLUT transform: inv-table searchsorted + paired trilerp ---
__global__ void transform_k(const float* __restrict__ lq, const float2* __restrict__ lut2,
                            const float* __restrict__ verts, float* __restrict__ out)
{
    int b = blockIdx.x >> 10;        // 1024 blocks per batch
    int blk = blockIdx.x & 1023;
    int tid = threadIdx.x;
    __shared__ float sv[3][DV];
    __shared__ int tbl[3][128];
    if (tid < 99) sv[tid/33][tid%33] = verts[b*99 + tid];
    __syncthreads();
    for (int t = tid; t < 384; t += 256) {
        int ch = t >> 7, e = t & 127;
        float edge = (float)e * (1.f/128.f);
        int idx = 0;
        #pragma unroll 8
        for (int m = 1; m <= 32; m++)
            if (sv[ch][m] <= edge) idx = m;
        tbl[ch][e] = idx;
    }
    __syncthreads();

    int n = (blk*256 + tid) * 4;
    const float* lqb = lq + (size_t)b*3*NPIX;
    float4 R  = *(const float4*)(lqb + n);
    float4 G  = *(const float4*)(lqb + NPIX + n);
    float4 Bl = *(const float4*)(lqb + 2*NPIX + n);

    float xr[4] = {R.x, R.y, R.z, R.w};
    float xg[4] = {G.x, G.y, G.z, G.w};
    float xb[4] = {Bl.x, Bl.y, Bl.z, Bl.w};
    float orr[4], org[4], orb[4];

    const float2* base = lut2 + (size_t)b*NLUT;

    #pragma unroll
    for (int px = 0; px < 4; px++) {
        float crd[3];
        float xs[3] = {xr[px], xg[px], xb[px]};
        #pragma unroll
        for (int ch = 0; ch < 3; ch++) {
            float x = xs[ch];
            int e = min((int)(x * 128.f), 127);
            int idx = tbl[ch][e];
            while (idx < 32 && sv[ch][idx+1] <= x) idx++;
            int lo = min(idx, 31);
            float vl = sv[ch][lo], vh = sv[ch][lo+1];
            float fr = (x - vl) / (vh - vl + 1e-8f);
            float cd = (float)lo + fr;
            crd[ch] = fminf(fmaxf(cd, 0.f), 32.f);
        }
        int i0 = min((int)crd[0], 31);
        int j0 = min((int)crd[1], 31);
        int k0 = min((int)crd[2], 31);
        float fr = crd[0] - (float)i0;
        float fg = crd[1] - (float)j0;
        float fb = crd[2] - (float)k0;

        const float2* p = base + i0*D2 + j0*DV + k0;
        #pragma unroll
        for (int c = 0; c < 3; c++) {
            const float2* pc = p + c*D3;
            float2 a00 = pc[0];
            float2 a01 = pc[DV];
            float2 a10 = pc[D2];
            float2 a11 = pc[D2+DV];
            float l00 = fmaf(fb, a00.y - a00.x, a00.x);
            float l01 = fmaf(fb, a01.y - a01.x, a01.x);
            float l10 = fmaf(fb, a10.y - a10.x, a10.x);
            float l11 = fmaf(fb, a11.y - a11.x, a11.x);
            float h0  = fmaf(fg, l01 - l00, l00);
            float h1  = fmaf(fg, l11 - l10, l10);
            float r   = fmaf(fr, h1 - h0, h0);
            r = fminf(fmaxf(r, 0.f), 1.f);
            if (c == 0) orr[px] = r; else if (c == 1) org[px] = r; else orb[px] = r;
        }
    }

    float* ob = out + (size_t)b*3*NPIX + n;
    *(float4*)(ob)          = make_float4(orr[0], orr[1], orr[2], orr[3]);
    *(float4*)(ob + NPIX)   = make_float4(org[0], org[1], org[2], org[3]);
    *(float4*)(ob + 2*NPIX) = make_float4(orb[0], orb[1], orb[2], orb[3]);
}

// ---------------- host launcher ----------------------------------------------
extern "C" void kernel_launch(void* const* d_in, const int* in_sizes, int n_in,
                              void* d_out, int out_size)
{
    const float* lq  = (const float*)d_in[0];
    const float* w1  = (const float*)d_in[1];
    const float* b1  = (const float*)d_in[2];
    const float* g1  = (const float*)d_in[3];
    const float* be1 = (const float*)d_in[4];
    const float* w2  = (const float*)d_in[5];
    const float* b2  = (const float*)d_in[6];
    const float* g2  = (const float*)d_in[7];
    const float* be2 = (const float*)d_in[8];
    const float* w3  = (const float*)d_in[9];
    const float* b3  = (const float*)d_in[10];
    const float* g3  = (const float*)d_in[11];
    const float* be3 = (const float*)d_in[12];
    const float* w4  = (const float*)d_in[13];
    const float* b4  = (const float*)d_in[14];
    const float* g4  = (const float*)d_in[15];
    const float* be4 = (const float*)d_in[16];
    const float* w5  = (const float*)d_in[17];
    const float* b5  = (const float*)d_in[18];
    const float* lw  = (const float*)d_in[19];
    const float* lb  = (const float*)d_in[20];
    const float* bw  = (const float*)d_in[21];
    const float* aw  = (const float*)d_in[22];
    const float* ab  = (const float*)d_in[23];

    float *res, *x1, *x2, *x3, *x4, *codes, *stats, *wts, *verts;
    float2* lut2;
    cudaGetSymbolAddress((void**)&res,   g_resized);
    cudaGetSymbolAddress((void**)&x1,    g_x1);
    cudaGetSymbolAddress((void**)&x2,    g_x2);
    cudaGetSymbolAddress((void**)&x3,    g_x3);
    cudaGetSymbolAddress((void**)&x4,    g_x4);
    cudaGetSymbolAddress((void**)&codes, g_codes);
    cudaGetSymbolAddress((void**)&stats, g_stats);
    cudaGetSymbolAddress((void**)&wts,   g_wts);
    cudaGetSymbolAddress((void**)&verts, g_verts);
    cudaGetSymbolAddress((void**)&lut2,  g_luts2);

    float* ss1 = stats;          // 4*16*2  = 128
    float* ss2 = stats + 128;    // 4*32*2  = 256
    float* ss3 = stats + 384;    // 4*64*2  = 512
    float* ss4 = stats + 896;    // 4*128*2 = 1024

    float* out = (float*)d_out;
    const int OFF_W = B*3*NPIX;          // 12582912
    const int OFF_V = OFF_W + B*3;       // +12

    zero_k<<<8, 256>>>(stats, 1920);

    resize_k<<<(B*3*256*256 + 255)/256, 256>>>(lq, res);

    conv_k<3, 16, 8, 256, 128, false><<<dim3(64, 2, B), 256>>>(
        res, w1, b1, nullptr, nullptr, nullptr, ss1, x1);

    conv_k<16, 32, 4, 128, 64, true><<<dim3(16, 8, B), 256>>>(
        x1, w2, b2, ss1, g1, be1, ss2, x2);

    conv_k<32, 64, 4, 64, 32, true><<<dim3(4, 16, B), 256>>>(
        x2, w3, b3, ss2, g2, be2, ss3, x3);

    conv_k<64, 128, 4, 32, 16, true><<<dim3(1, 32, B), 256>>>(
        x3, w4, b4, ss3, g3, be3, ss4, x4);

    conv5_pool_k<<<dim3(32, B), 64>>>(x4, w5, b5, ss4, g4, be4, codes);

    mlp_k<<<B, 128>>>(codes, lw, lb, aw, ab, wts, verts, out + OFF_W, out + OFF_V);

    luts2_k<<<(B*NLUT + 255)/256, 256>>>(bw, wts, lut2);

    transform_k<<<B*1024, 256>>>(lq, lut2, verts, out);
}